// round 1
// baseline (speedup 1.0000x reference)
#include <cuda_runtime.h>

#define VV 50257
#define EE 256
#define HH 512
#define BB 64
#define LL 64
#define SOS_TOK 2

#define VT 128
#define KC 32
#define LTHREADS 256
#define NBLK ((VV + VT - 1) / VT)   /* 393 */

// Ping-pong hidden state and packed argmax accumulators (128B-padded per row).
__device__ float g_h[2][BB * HH];
__device__ unsigned long long g_amax[2][BB * 16];

__device__ __forceinline__ unsigned int ofloat(float f) {
    unsigned int u = __float_as_uint(f);
    return (u & 0x80000000u) ? ~u : (u | 0x80000000u);
}

__device__ __forceinline__ unsigned long long pack_dup(float f) {
    unsigned long long d;
    unsigned int r = __float_as_uint(f);
    asm("mov.b64 %0, {%1, %1};" : "=l"(d) : "r"(r));
    return d;
}

__device__ __forceinline__ void ffma2(unsigned long long &acc,
                                      unsigned long long a,
                                      unsigned long long b) {
    asm("fma.rn.f32x2 %0, %1, %2, %0;" : "+l"(acc) : "l"(a), "l"(b));
}

// ---------------------------------------------------------------------------
// GRU step: one block handles 2 batch rows x 128 gate columns.
// grid (32, 4), 128 threads.
// ---------------------------------------------------------------------------
__global__ __launch_bounds__(128) void gru_kernel(
    int step, const float* __restrict__ h0, const float* __restrict__ emb,
    const float* __restrict__ Wih, const float* __restrict__ Whh,
    const float* __restrict__ bih, const float* __restrict__ bhh)
{
    __shared__ float xs[2][EE];
    __shared__ float hs[2][HH];
    __shared__ int toks[2];

    const int bp  = blockIdx.x;     // batch pair 0..31
    const int jg  = blockIdx.y;     // gate-column group 0..3
    const int tid = threadIdx.x;    // 0..127
    const int j   = jg * 128 + tid; // gate column 0..511
    const int wsel = step & 1;
    const int rsel = (step ^ 1) & 1;

    // Reset argmax accumulators for THIS step (logits kernel of this step writes them).
    if (bp == 0 && jg == 0 && tid < BB) g_amax[wsel][tid * 16] = 0ULL;

    // Decode previous tokens for this block's two rows.
    if (tid < 2) {
        int tok = SOS_TOK;
        if (step > 0) {
            unsigned long long p = g_amax[rsel][(bp * 2 + tid) * 16];
            tok = (int)(~(unsigned int)(p & 0xFFFFFFFFull));
        }
        toks[tid] = tok;
    }
    __syncthreads();

    // Stage x = emb[tok] (2 x 256) and h_prev (2 x 512) into smem.
    {
        int r = tid >> 6, c = tid & 63;
        ((float4*)xs[r])[c] = ((const float4*)emb)[(size_t)toks[r] * (EE / 4) + c];
    }
#pragma unroll
    for (int i = 0; i < 2; i++) {
        int li = tid + i * 128;
        int r = li >> 7, c = li & 127;
        const float* src = (step == 0) ? (h0 + (size_t)(bp * 2 + r) * HH)
                                       : (g_h[rsel] + (size_t)(bp * 2 + r) * HH);
        ((float4*)hs[r])[c] = ((const float4*)src)[c];
    }
    __syncthreads();

    float ir0 = 0.f, iz0 = 0.f, in0 = 0.f;
    float ir1 = 0.f, iz1 = 0.f, in1 = 0.f;
    {
        const float4* wr = (const float4*)(Wih + (size_t)j * EE);
        const float4* wz = (const float4*)(Wih + (size_t)(HH + j) * EE);
        const float4* wn = (const float4*)(Wih + (size_t)(2 * HH + j) * EE);
        const float4* x0 = (const float4*)xs[0];
        const float4* x1 = (const float4*)xs[1];
#pragma unroll 4
        for (int k = 0; k < EE / 4; k++) {
            float4 a = wr[k], b = wz[k], c = wn[k];
            float4 u = x0[k], v = x1[k];
            ir0 += a.x * u.x + a.y * u.y + a.z * u.z + a.w * u.w;
            iz0 += b.x * u.x + b.y * u.y + b.z * u.z + b.w * u.w;
            in0 += c.x * u.x + c.y * u.y + c.z * u.z + c.w * u.w;
            ir1 += a.x * v.x + a.y * v.y + a.z * v.z + a.w * v.w;
            iz1 += b.x * v.x + b.y * v.y + b.z * v.z + b.w * v.w;
            in1 += c.x * v.x + c.y * v.y + c.z * v.z + c.w * v.w;
        }
    }

    float hr0 = 0.f, hz0 = 0.f, hn0 = 0.f;
    float hr1 = 0.f, hz1 = 0.f, hn1 = 0.f;
    {
        const float4* wr = (const float4*)(Whh + (size_t)j * HH);
        const float4* wz = (const float4*)(Whh + (size_t)(HH + j) * HH);
        const float4* wn = (const float4*)(Whh + (size_t)(2 * HH + j) * HH);
        const float4* h0s = (const float4*)hs[0];
        const float4* h1s = (const float4*)hs[1];
#pragma unroll 4
        for (int k = 0; k < HH / 4; k++) {
            float4 a = wr[k], b = wz[k], c = wn[k];
            float4 u = h0s[k], v = h1s[k];
            hr0 += a.x * u.x + a.y * u.y + a.z * u.z + a.w * u.w;
            hz0 += b.x * u.x + b.y * u.y + b.z * u.z + b.w * u.w;
            hn0 += c.x * u.x + c.y * u.y + c.z * u.z + c.w * u.w;
            hr1 += a.x * v.x + a.y * v.y + a.z * v.z + a.w * v.w;
            hz1 += b.x * v.x + b.y * v.y + b.z * v.z + b.w * v.w;
            hn1 += c.x * v.x + c.y * v.y + c.z * v.z + c.w * v.w;
        }
    }

    const float bir = bih[j], biz = bih[HH + j], bin = bih[2 * HH + j];
    const float bhr = bhh[j], bhz = bhh[HH + j], bhn = bhh[2 * HH + j];
    float* hout = g_h[wsel];
    {
        float rr = 1.f / (1.f + expf(-(ir0 + bir + hr0 + bhr)));
        float zz = 1.f / (1.f + expf(-(iz0 + biz + hz0 + bhz)));
        float nn = tanhf(in0 + bin + rr * (hn0 + bhn));
        hout[(size_t)(bp * 2 + 0) * HH + j] = (1.f - zz) * nn + zz * hs[0][j];
    }
    {
        float rr = 1.f / (1.f + expf(-(ir1 + bir + hr1 + bhr)));
        float zz = 1.f / (1.f + expf(-(iz1 + biz + hz1 + bhz)));
        float nn = tanhf(in1 + bin + rr * (hn1 + bhn));
        hout[(size_t)(bp * 2 + 1) * HH + j] = (1.f - zz) * nn + zz * hs[1][j];
    }
}

// ---------------------------------------------------------------------------
// Classifier GEMM + fused argmax. Tile: 64 B x 128 V, K staged in 32-chunks.
// Per-thread: 8 b (as 4 packed pairs) x 4 v, fma.rn.f32x2 accumulation.
// grid (393), 256 threads.
// ---------------------------------------------------------------------------
__global__ __launch_bounds__(LTHREADS) void logits_kernel(
    int step, const float* __restrict__ Wc, const float* __restrict__ bc,
    float* __restrict__ out_all)
{
    __shared__ float Wsm[KC][VT];
    __shared__ float Hsm[KC][BB];

    const int tid = threadIdx.x;
    const int tx = tid & 31;   // v lane
    const int ty = tid >> 5;   // b group (warp id)
    const int v0 = blockIdx.x * VT;
    const float* hbuf = g_h[step & 1];
    float* out = out_all + (size_t)step * BB * VV;

    unsigned long long acc[4][4];  // [b_pair][v]
#pragma unroll
    for (int i = 0; i < 4; i++)
#pragma unroll
        for (int q = 0; q < 4; q++) acc[i][q] = 0ULL;

    for (int kc = 0; kc < HH; kc += KC) {
        __syncthreads();
        // W tile: 128 rows x 32 k (8 float4/row); lane-consecutive-in-v stores.
#pragma unroll
        for (int i = 0; i < 4; i++) {
            int li = tid + i * LTHREADS;   // 0..1023
            int c4 = li >> 7;              // 0..7
            int r  = li & 127;             // v row in tile
            int v  = v0 + r;
            float4 w = make_float4(0.f, 0.f, 0.f, 0.f);
            if (v < VV)
                w = ((const float4*)(Wc + (size_t)v * HH + kc))[c4];
            int k0 = c4 * 4;
            Wsm[k0 + 0][r] = w.x;
            Wsm[k0 + 1][r] = w.y;
            Wsm[k0 + 2][r] = w.z;
            Wsm[k0 + 3][r] = w.w;
        }
        // H tile: 64 rows x 32 k.
#pragma unroll
        for (int i = 0; i < 2; i++) {
            int li = tid + i * LTHREADS;   // 0..511
            int c4 = li >> 6;              // 0..7
            int r  = li & 63;              // b row
            float4 hv = ((const float4*)(hbuf + (size_t)r * HH + kc))[c4];
            int k0 = c4 * 4;
            Hsm[k0 + 0][r] = hv.x;
            Hsm[k0 + 1][r] = hv.y;
            Hsm[k0 + 2][r] = hv.z;
            Hsm[k0 + 3][r] = hv.w;
        }
        __syncthreads();

#pragma unroll 8
        for (int k = 0; k < KC; k++) {
            float4 wv = *(const float4*)&Wsm[k][tx * 4];
            unsigned long long wd0 = pack_dup(wv.x);
            unsigned long long wd1 = pack_dup(wv.y);
            unsigned long long wd2 = pack_dup(wv.z);
            unsigned long long wd3 = pack_dup(wv.w);
            const unsigned long long* hp =
                (const unsigned long long*)&Hsm[k][ty * 8];
#pragma unroll
            for (int bp = 0; bp < 4; bp++) {
                unsigned long long h2 = hp[bp];   // (h[b_even], h[b_odd])
                ffma2(acc[bp][0], h2, wd0);
                ffma2(acc[bp][1], h2, wd1);
                ffma2(acc[bp][2], h2, wd2);
                ffma2(acc[bp][3], h2, wd3);
            }
        }
    }

    // Unpack, add bias, store, and fold argmax.
    float logit[8][4];
#pragma unroll
    for (int bp = 0; bp < 4; bp++)
#pragma unroll
        for (int vi = 0; vi < 4; vi++) {
            unsigned long long u = acc[bp][vi];
            logit[bp * 2 + 0][vi] = __uint_as_float((unsigned int)u);
            logit[bp * 2 + 1][vi] = __uint_as_float((unsigned int)(u >> 32));
        }

    float bias[4];
#pragma unroll
    for (int vi = 0; vi < 4; vi++) {
        int v = v0 + tx * 4 + vi;
        bias[vi] = (v < VV) ? bc[v] : 0.f;
    }

    unsigned long long key[8];
#pragma unroll
    for (int b8 = 0; b8 < 8; b8++) {
        unsigned long long best = 0ULL;
        int gb = ty * 8 + b8;
        float* orow = out + (size_t)gb * VV;
#pragma unroll
        for (int vi = 0; vi < 4; vi++) {
            int v = v0 + tx * 4 + vi;
            if (v < VV) {
                float val = logit[b8][vi] + bias[vi];
                orow[v] = val;
                unsigned long long kk =
                    ((unsigned long long)ofloat(val) << 32) |
                    (unsigned int)(~(unsigned int)v);   // first-max tie-break
                if (kk > best) best = kk;
            }
        }
        key[b8] = best;
    }

#pragma unroll
    for (int off = 16; off > 0; off >>= 1)
#pragma unroll
        for (int b8 = 0; b8 < 8; b8++) {
            unsigned long long o = __shfl_down_sync(0xffffffffu, key[b8], off);
            if (o > key[b8]) key[b8] = o;
        }
    if (tx == 0) {
#pragma unroll
        for (int b8 = 0; b8 < 8; b8++)
            atomicMax(&g_amax[step & 1][(ty * 8 + b8) * 16], key[b8]);
    }
}

// ---------------------------------------------------------------------------
extern "C" void kernel_launch(void* const* d_in, const int* in_sizes, int n_in,
                              void* d_out, int out_size) {
    const float* h0   = (const float*)d_in[0];
    const float* emb  = (const float*)d_in[1];
    const float* W_ih = (const float*)d_in[2];
    const float* W_hh = (const float*)d_in[3];
    const float* b_ih = (const float*)d_in[4];
    const float* b_hh = (const float*)d_in[5];
    const float* Wc   = (const float*)d_in[6];
    const float* bc   = (const float*)d_in[7];
    float* out = (float*)d_out;

    dim3 ggrid(32, 4), gblk(128);
    dim3 lgrid(NBLK), lblk(LTHREADS);
    for (int s = 0; s < LL; s++) {
        gru_kernel<<<ggrid, gblk>>>(s, h0, emb, W_ih, W_hh, b_ih, b_hh);
        logits_kernel<<<lgrid, lblk>>>(s, Wc, bc, out);
    }
}